// round 6
// baseline (speedup 1.0000x reference)
#include <cuda_runtime.h>
#include <cstdint>

#define S_DIM 4
#define N_DIM 4096
#define D_DIM 64

// Split-bf16 scratch, pair-packed along k: word = (bf16 elem 2p | bf16 elem 2p+1 << 16)
// hi = rne-bf16(x), lo = rne-bf16(x - hi)
#define PAIR_WORDS (S_DIM * N_DIM * D_DIM / 2)
__device__ uint32_t g_Xh[PAIR_WORDS];
__device__ uint32_t g_Xl[PAIR_WORDS];
__device__ uint32_t g_Qh[PAIR_WORDS];
__device__ uint32_t g_Ql[PAIR_WORDS];

__device__ __forceinline__ uint32_t smem_u32(const void* p) {
    uint32_t a;
    asm("{ .reg .u64 t; cvta.to.shared.u64 t, %1; cvt.u32.u64 %0, t; }"
        : "=r"(a) : "l"(p));
    return a;
}
// pack two fp32 -> bf16x2 word (lo16 = a, hi16 = b)
__device__ __forceinline__ uint32_t bf16x2(float a, float b) {
    uint32_t d;
    asm("cvt.rn.bf16x2.f32 %0, %1, %2;" : "=r"(d) : "f"(b), "f"(a));
    return d;
}
// split two fp32 into (hi-word, lo-word)
__device__ __forceinline__ void split2(float a, float b, uint32_t& hw, uint32_t& lw) {
    hw = bf16x2(a, b);
    float ha = __uint_as_float(hw << 16);
    float hb = __uint_as_float(hw & 0xFFFF0000u);
    lw = bf16x2(a - ha, b - hb);
}

// bf16 mma m16n8k16 (baseline PTX, valid on compute_103)
__device__ __forceinline__ void mma_bf16(float d[4], const uint32_t a[4], const uint32_t b[2]) {
    asm volatile(
        "mma.sync.aligned.m16n8k16.row.col.f32.bf16.bf16.f32 "
        "{%0,%1,%2,%3}, {%4,%5,%6,%7}, {%8,%9}, {%0,%1,%2,%3};"
        : "+f"(d[0]), "+f"(d[1]), "+f"(d[2]), "+f"(d[3])
        : "r"(a[0]), "r"(a[1]), "r"(a[2]), "r"(a[3]), "r"(b[0]), "r"(b[1]));
}

// ---------------------------------------------------------------------------
// Prep A: split x1 into hi/lo pair arrays
// ---------------------------------------------------------------------------
__global__ __launch_bounds__(256) void split_x1_kernel(const float* __restrict__ x1) {
    int i = blockIdx.x * 256 + threadIdx.x;       // float4 index = uint2 pair index
    float4 v = reinterpret_cast<const float4*>(x1)[i];
    uint2 h, l;
    split2(v.x, v.y, h.x, l.x);
    split2(v.z, v.w, h.y, l.y);
    reinterpret_cast<uint2*>(g_Xh)[i] = h;
    reinterpret_cast<uint2*>(g_Xl)[i] = l;
}

// ---------------------------------------------------------------------------
// Prep B: Q[r,d] = sum_e x0[r,e] * W[d,e]  (SIMT fp32), write split pair arrays
// ---------------------------------------------------------------------------
__device__ __forceinline__ void load_tile_transposed64(
    const float* __restrict__ gsrc, float* sdst, int t)
{
    const float4* g4 = reinterpret_cast<const float4*>(gsrc);
#pragma unroll
    for (int p = 0; p < 4; ++p) {
        int f4 = p * 256 + t;
        int x  = f4 >> 4;
        int k4 = (f4 & 15) << 2;
        float4 v = g4[f4];
        float vv[4] = {v.x, v.y, v.z, v.w};
#pragma unroll
        for (int q = 0; q < 4; ++q) {
            int k  = k4 + q;
            int c4 = (x >> 2) ^ ((k >> 2) & 15);
            sdst[k * 64 + c4 * 4 + (x & 3)] = vv[q];
        }
    }
}

__global__ __launch_bounds__(256) void q_kernel(
    const float* __restrict__ x0, const float* __restrict__ W)
{
    __shared__ float Xs[64 * 64];
    __shared__ float Ws[64 * 64];
    int t  = threadIdx.x;
    int r0 = blockIdx.x * 64;

    load_tile_transposed64(x0 + (size_t)r0 * 64, Xs, t);
    load_tile_transposed64(W, Ws, t);
    __syncthreads();

    int tx = t & 15, ty = t >> 4;
    float acc[4][4] = {};
#pragma unroll
    for (int k = 0; k < 64; ++k) {
        int sw = (k >> 2) & 15;
        float4 a = *reinterpret_cast<const float4*>(&Xs[k * 64 + ((ty ^ sw) << 2)]);
        float4 b = *reinterpret_cast<const float4*>(&Ws[k * 64 + ((tx ^ sw) << 2)]);
        float av[4] = {a.x, a.y, a.z, a.w};
        float bv[4] = {b.x, b.y, b.z, b.w};
#pragma unroll
        for (int ra = 0; ra < 4; ++ra)
#pragma unroll
            for (int rb = 0; rb < 4; ++rb)
                acc[ra][rb] += av[ra] * bv[rb];
    }

#pragma unroll
    for (int ra = 0; ra < 4; ++ra) {
        int r = r0 + ty * 4 + ra;
        uint2 h, l;
        split2(acc[ra][0], acc[ra][1], h.x, l.x);
        split2(acc[ra][2], acc[ra][3], h.y, l.y);
        int p0 = r * 32 + 2 * tx;       // pair index (even)
        *reinterpret_cast<uint2*>(&g_Qh[p0]) = h;
        *reinterpret_cast<uint2*>(&g_Ql[p0]) = l;
    }
}

// ---------------------------------------------------------------------------
// Stage 2: 3-pass split-bf16 mma.sync GEMM (hh + lh + hl).
// CTA = 128x128 C tile, 256 threads = 8 warps (2m x 4n), warp = 64x32.
// Smem: 4 tiles [128 rows][36 pair-words] (A-hi,A-lo,B-hi,B-lo) = 73.7 KB.
// 3 CTAs/SM; mt-outer loop -> 16-reg accumulator + interleaved store bursts.
// ---------------------------------------------------------------------------
#define PADW 36
#define TILE_W (128 * PADW)
#define SMEM_DYN (4 * TILE_W * 4)

__device__ __forceinline__ void fill_tile_async(
    const uint32_t* __restrict__ gsrc, uint32_t* sdst, int t)
{
#pragma unroll
    for (int it = 0; it < 4; ++it) {
        int f4 = it * 256 + t;          // 0..1023 16B chunks (128 rows x 8)
        int r  = f4 >> 3;
        int c4 = f4 & 7;
        uint32_t sa = smem_u32(&sdst[r * PADW + c4 * 4]);
        asm volatile("cp.async.cg.shared.global [%0], [%1], 16;"
                     :: "r"(sa), "l"(gsrc + f4 * 4) : "memory");
    }
}

__global__ __launch_bounds__(256, 3) void bilinear_mma_kernel(
    const float* __restrict__ bias, float* __restrict__ out)
{
    extern __shared__ uint32_t sm[];
    uint32_t* Ah = sm;
    uint32_t* Al = sm + TILE_W;
    uint32_t* Bh = sm + 2 * TILE_W;
    uint32_t* Bl = sm + 3 * TILE_W;

    int t    = threadIdx.x;
    int warp = t >> 5;
    int lane = t & 31;
    int wm   = warp >> 2;      // 0..1  (m, 64 rows)
    int wn   = warp & 3;       // 0..3  (n, 32 cols)
    int g    = lane >> 2;      // 0..7
    int tg   = lane & 3;       // 0..3

    int s  = blockIdx.z;
    int i0 = blockIdx.y * 128;
    int j0 = blockIdx.x * 128;

    size_t abase = (size_t)(s * N_DIM + i0) * (D_DIM / 2);
    size_t bbase = (size_t)(s * N_DIM + j0) * (D_DIM / 2);
    fill_tile_async(g_Xh + abase, Ah, t);
    fill_tile_async(g_Xl + abase, Al, t);
    fill_tile_async(g_Qh + bbase, Bh, t);
    fill_tile_async(g_Ql + bbase, Bl, t);
    asm volatile("cp.async.commit_group;" ::: "memory");
    asm volatile("cp.async.wait_group 0;" ::: "memory");
    __syncthreads();

    // lane-mapped bases: word index mod 32 = 4g+tg = lane -> conflict-free
    const uint32_t* pAh = Ah + (wm * 64 + g) * PADW + tg;
    const uint32_t* pAl = Al + (wm * 64 + g) * PADW + tg;
    const uint32_t* pBh = Bh + (wn * 32 + g) * PADW + tg;
    const uint32_t* pBl = Bl + (wn * 32 + g) * PADW + tg;

    float bv = __ldg(bias);
    const size_t batch_stride = (size_t)S_DIM * N_DIM * N_DIM;

#pragma unroll
    for (int mt = 0; mt < 4; ++mt) {
        float acc[4][4];
#pragma unroll
        for (int a = 0; a < 4; ++a)
#pragma unroll
            for (int c = 0; c < 4; ++c) acc[a][c] = 0.0f;

#pragma unroll
        for (int kt = 0; kt < 4; ++kt) {
            int k0 = kt * 8;            // pair offset
            uint32_t ah[4], al[4];
#pragma unroll
            for (int q = 0; q < 4; ++q) {
                int off = (mt * 16 + 8 * (q & 1)) * PADW + k0 + 4 * (q >> 1);
                ah[q] = pAh[off];
                al[q] = pAl[off];
            }
#pragma unroll
            for (int nt = 0; nt < 4; ++nt) {
                uint32_t bh[2], bl[2];
#pragma unroll
                for (int q = 0; q < 2; ++q) {
                    int off = (nt * 8) * PADW + k0 + 4 * q;
                    bh[q] = pBh[off];
                    bl[q] = pBl[off];
                }
                mma_bf16(acc[nt], ah, bh);   // hi*hi
                mma_bf16(acc[nt], al, bh);   // lo*hi
                mma_bf16(acc[nt], ah, bl);   // hi*lo
            }
        }

        // Store this 16-row slice (interleaved with next mt's compute)
#pragma unroll
        for (int h = 0; h < 2; ++h) {
            int i = i0 + wm * 64 + mt * 16 + g + 8 * h;
            size_t rowoff = ((size_t)s * N_DIM + i) * N_DIM;
#pragma unroll
            for (int nt = 0; nt < 4; ++nt) {
                int j = j0 + wn * 32 + nt * 8 + 2 * tg;
                float2 v;
                v.x = acc[nt][2 * h + 0] + bv;
                v.y = acc[nt][2 * h + 1] + bv;
                __stcs(reinterpret_cast<float2*>(&out[rowoff + j]), v);
                __stcs(reinterpret_cast<float2*>(&out[rowoff + j + batch_stride]), v);
            }
        }
    }
}

extern "C" void kernel_launch(void* const* d_in, const int* in_sizes, int n_in,
                              void* d_out, int out_size)
{
    const float* x0   = (const float*)d_in[0];  // tensor0 (S,N,D)
    const float* x1   = (const float*)d_in[1];  // tensor1 (S,N,D)
    const float* W    = (const float*)d_in[2];  // kernel  (D,D)
    const float* bias = (const float*)d_in[3];  // scalar
    float* out = (float*)d_out;                 // (2,S,N,N)

    cudaFuncSetAttribute(bilinear_mma_kernel,
                         cudaFuncAttributeMaxDynamicSharedMemorySize, SMEM_DYN);

    split_x1_kernel<<<(S_DIM * N_DIM * D_DIM) / (256 * 4), 256>>>(x1);
    q_kernel<<<(S_DIM * N_DIM) / 64, 256>>>(x0, W);

    dim3 grid(N_DIM / 128, N_DIM / 128, S_DIM);
    bilinear_mma_kernel<<<grid, 256, SMEM_DYN>>>(bias, out);
}

// round 7
// speedup vs baseline: 1.3633x; 1.3633x over previous
#include <cuda_runtime.h>
#include <cstdint>

#define S_DIM 4
#define N_DIM 4096
#define D_DIM 64

// Split-bf16 scratch, pair-packed along k: word = (bf16 elem 2p | bf16 elem 2p+1 << 16)
// hi = rne-bf16(x), lo = rne-bf16(x - hi)
#define PAIR_WORDS (S_DIM * N_DIM * D_DIM / 2)
__device__ uint32_t g_Xh[PAIR_WORDS];
__device__ uint32_t g_Xl[PAIR_WORDS];
__device__ uint32_t g_Qh[PAIR_WORDS];
__device__ uint32_t g_Ql[PAIR_WORDS];

__device__ __forceinline__ uint32_t smem_u32(const void* p) {
    uint32_t a;
    asm("{ .reg .u64 t; cvta.to.shared.u64 t, %1; cvt.u32.u64 %0, t; }"
        : "=r"(a) : "l"(p));
    return a;
}
// pack two fp32 -> bf16x2 word (lo16 = a, hi16 = b)
__device__ __forceinline__ uint32_t bf16x2(float a, float b) {
    uint32_t d;
    asm("cvt.rn.bf16x2.f32 %0, %1, %2;" : "=r"(d) : "f"(b), "f"(a));
    return d;
}
// split two fp32 into (hi-word, lo-word)
__device__ __forceinline__ void split2(float a, float b, uint32_t& hw, uint32_t& lw) {
    hw = bf16x2(a, b);
    float ha = __uint_as_float(hw << 16);
    float hb = __uint_as_float(hw & 0xFFFF0000u);
    lw = bf16x2(a - ha, b - hb);
}

// bf16 mma m16n8k16 (baseline PTX, valid on compute_103)
__device__ __forceinline__ void mma_bf16(float d[4], const uint32_t a[4], const uint32_t b[2]) {
    asm volatile(
        "mma.sync.aligned.m16n8k16.row.col.f32.bf16.bf16.f32 "
        "{%0,%1,%2,%3}, {%4,%5,%6,%7}, {%8,%9}, {%0,%1,%2,%3};"
        : "+f"(d[0]), "+f"(d[1]), "+f"(d[2]), "+f"(d[3])
        : "r"(a[0]), "r"(a[1]), "r"(a[2]), "r"(a[3]), "r"(b[0]), "r"(b[1]));
}

// ---------------------------------------------------------------------------
// Prep A: split x1 into hi/lo pair arrays
// ---------------------------------------------------------------------------
__global__ __launch_bounds__(256) void split_x1_kernel(const float* __restrict__ x1) {
    int i = blockIdx.x * 256 + threadIdx.x;       // float4 index = uint2 pair index
    float4 v = reinterpret_cast<const float4*>(x1)[i];
    uint2 h, l;
    split2(v.x, v.y, h.x, l.x);
    split2(v.z, v.w, h.y, l.y);
    reinterpret_cast<uint2*>(g_Xh)[i] = h;
    reinterpret_cast<uint2*>(g_Xl)[i] = l;
}

// ---------------------------------------------------------------------------
// Prep B: Q[r,d] = sum_e x0[r,e] * W[d,e]  (SIMT fp32), write split pair arrays
// ---------------------------------------------------------------------------
__device__ __forceinline__ void load_tile_transposed64(
    const float* __restrict__ gsrc, float* sdst, int t)
{
    const float4* g4 = reinterpret_cast<const float4*>(gsrc);
#pragma unroll
    for (int p = 0; p < 4; ++p) {
        int f4 = p * 256 + t;
        int x  = f4 >> 4;
        int k4 = (f4 & 15) << 2;
        float4 v = g4[f4];
        float vv[4] = {v.x, v.y, v.z, v.w};
#pragma unroll
        for (int q = 0; q < 4; ++q) {
            int k  = k4 + q;
            int c4 = (x >> 2) ^ ((k >> 2) & 15);
            sdst[k * 64 + c4 * 4 + (x & 3)] = vv[q];
        }
    }
}

__global__ __launch_bounds__(256) void q_kernel(
    const float* __restrict__ x0, const float* __restrict__ W)
{
    __shared__ float Xs[64 * 64];
    __shared__ float Ws[64 * 64];
    int t  = threadIdx.x;
    int r0 = blockIdx.x * 64;

    load_tile_transposed64(x0 + (size_t)r0 * 64, Xs, t);
    load_tile_transposed64(W, Ws, t);
    __syncthreads();

    int tx = t & 15, ty = t >> 4;
    float acc[4][4] = {};
#pragma unroll
    for (int k = 0; k < 64; ++k) {
        int sw = (k >> 2) & 15;
        float4 a = *reinterpret_cast<const float4*>(&Xs[k * 64 + ((ty ^ sw) << 2)]);
        float4 b = *reinterpret_cast<const float4*>(&Ws[k * 64 + ((tx ^ sw) << 2)]);
        float av[4] = {a.x, a.y, a.z, a.w};
        float bv[4] = {b.x, b.y, b.z, b.w};
#pragma unroll
        for (int ra = 0; ra < 4; ++ra)
#pragma unroll
            for (int rb = 0; rb < 4; ++rb)
                acc[ra][rb] += av[ra] * bv[rb];
    }

#pragma unroll
    for (int ra = 0; ra < 4; ++ra) {
        int r = r0 + ty * 4 + ra;
        uint2 h, l;
        split2(acc[ra][0], acc[ra][1], h.x, l.x);
        split2(acc[ra][2], acc[ra][3], h.y, l.y);
        int p0 = r * 32 + 2 * tx;       // pair index (even)
        *reinterpret_cast<uint2*>(&g_Qh[p0]) = h;
        *reinterpret_cast<uint2*>(&g_Ql[p0]) = l;
    }
}

// ---------------------------------------------------------------------------
// Stage 2: 3-pass split-bf16 mma.sync GEMM (hh + lh + hl).
// CTA = 128x128 C tile, 256 threads = 8 warps (2m x 4n), warp = 64x32.
// kt-outer loop, full 4x4x4 accumulator (ILP across 16 MMA targets),
// pass-major MMA issue (no consecutive MMAs share an accumulator).
// Smem: 4 tiles [128 rows][36 pair-words] = 73.7 KB -> 2 CTAs/SM.
// ---------------------------------------------------------------------------
#define PADW 36
#define TILE_W (128 * PADW)
#define SMEM_DYN (4 * TILE_W * 4)

__device__ __forceinline__ void fill_tile_async(
    const uint32_t* __restrict__ gsrc, uint32_t* sdst, int t)
{
#pragma unroll
    for (int it = 0; it < 4; ++it) {
        int f4 = it * 256 + t;          // 0..1023 16B chunks (128 rows x 8)
        int r  = f4 >> 3;
        int c4 = f4 & 7;
        uint32_t sa = smem_u32(&sdst[r * PADW + c4 * 4]);
        asm volatile("cp.async.cg.shared.global [%0], [%1], 16;"
                     :: "r"(sa), "l"(gsrc + f4 * 4) : "memory");
    }
}

__global__ __launch_bounds__(256, 2) void bilinear_mma_kernel(
    const float* __restrict__ bias, float* __restrict__ out)
{
    extern __shared__ uint32_t sm[];
    uint32_t* Ah = sm;
    uint32_t* Al = sm + TILE_W;
    uint32_t* Bh = sm + 2 * TILE_W;
    uint32_t* Bl = sm + 3 * TILE_W;

    int t    = threadIdx.x;
    int warp = t >> 5;
    int lane = t & 31;
    int wm   = warp >> 2;      // 0..1  (m, 64 rows)
    int wn   = warp & 3;       // 0..3  (n, 32 cols)
    int g    = lane >> 2;      // 0..7
    int tg   = lane & 3;       // 0..3

    int s  = blockIdx.z;
    int i0 = blockIdx.y * 128;
    int j0 = blockIdx.x * 128;

    size_t abase = (size_t)(s * N_DIM + i0) * (D_DIM / 2);
    size_t bbase = (size_t)(s * N_DIM + j0) * (D_DIM / 2);
    fill_tile_async(g_Xh + abase, Ah, t);
    fill_tile_async(g_Xl + abase, Al, t);
    fill_tile_async(g_Qh + bbase, Bh, t);
    fill_tile_async(g_Ql + bbase, Bl, t);
    asm volatile("cp.async.commit_group;" ::: "memory");
    asm volatile("cp.async.wait_group 0;" ::: "memory");
    __syncthreads();

    // lane-mapped bases: word index mod 32 = 4g+tg = lane -> conflict-free
    const uint32_t* pAh = Ah + (wm * 64 + g) * PADW + tg;
    const uint32_t* pAl = Al + (wm * 64 + g) * PADW + tg;
    const uint32_t* pBh = Bh + (wn * 32 + g) * PADW + tg;
    const uint32_t* pBl = Bl + (wn * 32 + g) * PADW + tg;

    float acc[4][4][4];
#pragma unroll
    for (int a = 0; a < 4; ++a)
#pragma unroll
        for (int b = 0; b < 4; ++b)
#pragma unroll
            for (int c = 0; c < 4; ++c) acc[a][b][c] = 0.0f;

#pragma unroll
    for (int kt = 0; kt < 4; ++kt) {
        int k0 = kt * 8;                // pair offset

        uint32_t ah[4][4], al[4][4];    // [mt][reg]
        uint32_t bh[4][2], bl[4][2];    // [nt][reg]
#pragma unroll
        for (int mt = 0; mt < 4; ++mt)
#pragma unroll
            for (int q = 0; q < 4; ++q) {
                int off = (mt * 16 + 8 * (q & 1)) * PADW + k0 + 4 * (q >> 1);
                ah[mt][q] = pAh[off];
                al[mt][q] = pAl[off];
            }
#pragma unroll
        for (int nt = 0; nt < 4; ++nt)
#pragma unroll
            for (int q = 0; q < 2; ++q) {
                int off = (nt * 8) * PADW + k0 + 4 * q;
                bh[nt][q] = pBh[off];
                bl[nt][q] = pBl[off];
            }

        // pass-major issue: 16 independent MMAs per pass
#pragma unroll
        for (int mt = 0; mt < 4; ++mt)
#pragma unroll
            for (int nt = 0; nt < 4; ++nt)
                mma_bf16(acc[mt][nt], ah[mt], bh[nt]);   // hi*hi
#pragma unroll
        for (int mt = 0; mt < 4; ++mt)
#pragma unroll
            for (int nt = 0; nt < 4; ++nt)
                mma_bf16(acc[mt][nt], al[mt], bh[nt]);   // lo*hi
#pragma unroll
        for (int mt = 0; mt < 4; ++mt)
#pragma unroll
            for (int nt = 0; nt < 4; ++nt)
                mma_bf16(acc[mt][nt], ah[mt], bl[nt]);   // hi*lo
    }

    float bv = __ldg(bias);
    const size_t batch_stride = (size_t)S_DIM * N_DIM * N_DIM;

    // Epilogue: c0,c1 -> (row g, cols 2tg,2tg+1); c2,c3 -> row g+8
#pragma unroll
    for (int mt = 0; mt < 4; ++mt) {
#pragma unroll
        for (int h = 0; h < 2; ++h) {
            int i = i0 + wm * 64 + mt * 16 + g + 8 * h;
            size_t rowoff = ((size_t)s * N_DIM + i) * N_DIM;
#pragma unroll
            for (int nt = 0; nt < 4; ++nt) {
                int j = j0 + wn * 32 + nt * 8 + 2 * tg;
                float2 v;
                v.x = acc[mt][nt][2 * h + 0] + bv;
                v.y = acc[mt][nt][2 * h + 1] + bv;
                __stcs(reinterpret_cast<float2*>(&out[rowoff + j]), v);
                __stcs(reinterpret_cast<float2*>(&out[rowoff + j + batch_stride]), v);
            }
        }
    }
}

extern "C" void kernel_launch(void* const* d_in, const int* in_sizes, int n_in,
                              void* d_out, int out_size)
{
    const float* x0   = (const float*)d_in[0];  // tensor0 (S,N,D)
    const float* x1   = (const float*)d_in[1];  // tensor1 (S,N,D)
    const float* W    = (const float*)d_in[2];  // kernel  (D,D)
    const float* bias = (const float*)d_in[3];  // scalar
    float* out = (float*)d_out;                 // (2,S,N,N)

    cudaFuncSetAttribute(bilinear_mma_kernel,
                         cudaFuncAttributeMaxDynamicSharedMemorySize, SMEM_DYN);

    split_x1_kernel<<<(S_DIM * N_DIM * D_DIM) / (256 * 4), 256>>>(x1);
    q_kernel<<<(S_DIM * N_DIM) / 64, 256>>>(x0, W);

    dim3 grid(N_DIM / 128, N_DIM / 128, S_DIM);
    bilinear_mma_kernel<<<grid, 256, SMEM_DYN>>>(bias, out);
}

// round 8
// speedup vs baseline: 1.3760x; 1.0093x over previous
#include <cuda_runtime.h>
#include <cstdint>

#define S_DIM 4
#define N_DIM 4096
#define D_DIM 64

// Split-bf16 scratch, pair-packed along k: word = (bf16 elem 2p | bf16 elem 2p+1 << 16)
// hi = rne-bf16(x), lo = rne-bf16(x - hi)
#define PAIR_WORDS (S_DIM * N_DIM * D_DIM / 2)
__device__ uint32_t g_Xh[PAIR_WORDS];
__device__ uint32_t g_Xl[PAIR_WORDS];
__device__ uint32_t g_Qh[PAIR_WORDS];
__device__ uint32_t g_Ql[PAIR_WORDS];

__device__ __forceinline__ uint32_t smem_u32(const void* p) {
    uint32_t a;
    asm("{ .reg .u64 t; cvta.to.shared.u64 t, %1; cvt.u32.u64 %0, t; }"
        : "=r"(a) : "l"(p));
    return a;
}
__device__ __forceinline__ uint32_t bf16x2(float a, float b) {
    uint32_t d;
    asm("cvt.rn.bf16x2.f32 %0, %1, %2;" : "=r"(d) : "f"(b), "f"(a));
    return d;
}
__device__ __forceinline__ void split2(float a, float b, uint32_t& hw, uint32_t& lw) {
    hw = bf16x2(a, b);
    float ha = __uint_as_float(hw << 16);
    float hb = __uint_as_float(hw & 0xFFFF0000u);
    lw = bf16x2(a - ha, b - hb);
}

// bf16 mma m16n8k16 (baseline PTX, valid on compute_103)
__device__ __forceinline__ void mma_bf16(float d[4], const uint32_t a[4], const uint32_t b[2]) {
    asm volatile(
        "mma.sync.aligned.m16n8k16.row.col.f32.bf16.bf16.f32 "
        "{%0,%1,%2,%3}, {%4,%5,%6,%7}, {%8,%9}, {%0,%1,%2,%3};"
        : "+f"(d[0]), "+f"(d[1]), "+f"(d[2]), "+f"(d[3])
        : "r"(a[0]), "r"(a[1]), "r"(a[2]), "r"(a[3]), "r"(b[0]), "r"(b[1]));
}
__device__ __forceinline__ void ldsm_x4(uint32_t r[4], uint32_t addr) {
    asm volatile("ldmatrix.sync.aligned.m8n8.x4.shared.b16 {%0,%1,%2,%3}, [%4];"
                 : "=r"(r[0]), "=r"(r[1]), "=r"(r[2]), "=r"(r[3]) : "r"(addr));
}
__device__ __forceinline__ void ldsm_x2(uint32_t r[2], uint32_t addr) {
    asm volatile("ldmatrix.sync.aligned.m8n8.x2.shared.b16 {%0,%1}, [%2];"
                 : "=r"(r[0]), "=r"(r[1]) : "r"(addr));
}

// ---------------------------------------------------------------------------
// Fused prep: blocks [0,256) compute Q + split; blocks [256,1280) split x1.
// ---------------------------------------------------------------------------
__device__ __forceinline__ void load_tile_transposed64(
    const float* __restrict__ gsrc, float* sdst, int t)
{
    const float4* g4 = reinterpret_cast<const float4*>(gsrc);
#pragma unroll
    for (int p = 0; p < 4; ++p) {
        int f4 = p * 256 + t;
        int x  = f4 >> 4;
        int k4 = (f4 & 15) << 2;
        float4 v = g4[f4];
        float vv[4] = {v.x, v.y, v.z, v.w};
#pragma unroll
        for (int q = 0; q < 4; ++q) {
            int k  = k4 + q;
            int c4 = (x >> 2) ^ ((k >> 2) & 15);
            sdst[k * 64 + c4 * 4 + (x & 3)] = vv[q];
        }
    }
}

__global__ __launch_bounds__(256) void prep_kernel(
    const float* __restrict__ x0, const float* __restrict__ x1,
    const float* __restrict__ W)
{
    __shared__ float Xs[64 * 64];
    __shared__ float Ws[64 * 64];
    int t = threadIdx.x;

    if (blockIdx.x >= 256) {
        // ---- split x1 ----
        int i = (blockIdx.x - 256) * 256 + t;     // float4 index = uint2 pair index
        float4 v = reinterpret_cast<const float4*>(x1)[i];
        uint2 h, l;
        split2(v.x, v.y, h.x, l.x);
        split2(v.z, v.w, h.y, l.y);
        reinterpret_cast<uint2*>(g_Xh)[i] = h;
        reinterpret_cast<uint2*>(g_Xl)[i] = l;
        return;
    }

    // ---- Q = x0 · Wᵀ, then split ----
    int r0 = blockIdx.x * 64;
    load_tile_transposed64(x0 + (size_t)r0 * 64, Xs, t);
    load_tile_transposed64(W, Ws, t);
    __syncthreads();

    int tx = t & 15, ty = t >> 4;
    float acc[4][4] = {};
#pragma unroll
    for (int k = 0; k < 64; ++k) {
        int sw = (k >> 2) & 15;
        float4 a = *reinterpret_cast<const float4*>(&Xs[k * 64 + ((ty ^ sw) << 2)]);
        float4 b = *reinterpret_cast<const float4*>(&Ws[k * 64 + ((tx ^ sw) << 2)]);
        float av[4] = {a.x, a.y, a.z, a.w};
        float bv[4] = {b.x, b.y, b.z, b.w};
#pragma unroll
        for (int ra = 0; ra < 4; ++ra)
#pragma unroll
            for (int rb = 0; rb < 4; ++rb)
                acc[ra][rb] += av[ra] * bv[rb];
    }

#pragma unroll
    for (int ra = 0; ra < 4; ++ra) {
        int r = r0 + ty * 4 + ra;
        uint2 h, l;
        split2(acc[ra][0], acc[ra][1], h.x, l.x);
        split2(acc[ra][2], acc[ra][3], h.y, l.y);
        int p0 = r * 32 + 2 * tx;       // pair index (even)
        *reinterpret_cast<uint2*>(&g_Qh[p0]) = h;
        *reinterpret_cast<uint2*>(&g_Ql[p0]) = l;
    }
}

// ---------------------------------------------------------------------------
// Stage 2: 3-pass split-bf16 mma.sync GEMM (hh + lh + hl).
// CTA = 128x128 C tile, 256 threads = 8 warps (2m x 4n), warp = 64x32.
// kt-outer, full 4x4x4 accumulator, pass-major MMA issue.
// Fragments via ldmatrix (16 instrs/warp/kt vs 48 scalar LDS).
// Smem: 4 tiles [128 rows][36 pair-words] = 73.7 KB -> 2 CTAs/SM.
// ---------------------------------------------------------------------------
#define PADW 36
#define TILE_W (128 * PADW)
#define SMEM_DYN (4 * TILE_W * 4)
#define A_MT_BYTES (16 * PADW * 4)      // 16 rows
#define B_NT_BYTES (8 * PADW * 4)       // 8 rows
#define KT_BYTES   32                   // 8 pair-words

__device__ __forceinline__ void fill_tile_async(
    const uint32_t* __restrict__ gsrc, uint32_t* sdst, int t)
{
#pragma unroll
    for (int it = 0; it < 4; ++it) {
        int f4 = it * 256 + t;          // 0..1023 16B chunks (128 rows x 8)
        int r  = f4 >> 3;
        int c4 = f4 & 7;
        uint32_t sa = smem_u32(&sdst[r * PADW + c4 * 4]);
        asm volatile("cp.async.cg.shared.global [%0], [%1], 16;"
                     :: "r"(sa), "l"(gsrc + f4 * 4) : "memory");
    }
}

__global__ __launch_bounds__(256, 2) void bilinear_mma_kernel(
    const float* __restrict__ bias, float* __restrict__ out)
{
    extern __shared__ uint32_t sm[];
    uint32_t* Ah = sm;
    uint32_t* Al = sm + TILE_W;
    uint32_t* Bh = sm + 2 * TILE_W;
    uint32_t* Bl = sm + 3 * TILE_W;

    int t    = threadIdx.x;
    int warp = t >> 5;
    int lane = t & 31;
    int wm   = warp >> 2;      // 0..1  (m, 64 rows)
    int wn   = warp & 3;       // 0..3  (n, 32 cols)
    int g    = lane >> 2;      // 0..7
    int tg   = lane & 3;       // 0..3

    int s  = blockIdx.z;
    int i0 = blockIdx.y * 128;
    int j0 = blockIdx.x * 128;

    size_t abase = (size_t)(s * N_DIM + i0) * (D_DIM / 2);
    size_t bbase = (size_t)(s * N_DIM + j0) * (D_DIM / 2);
    fill_tile_async(g_Xh + abase, Ah, t);
    fill_tile_async(g_Xl + abase, Al, t);
    fill_tile_async(g_Qh + bbase, Bh, t);
    fill_tile_async(g_Ql + bbase, Bl, t);
    asm volatile("cp.async.commit_group;" ::: "memory");
    asm volatile("cp.async.wait_group 0;" ::: "memory");
    __syncthreads();

    // ldmatrix per-lane row addressing
    // A (x4): matrices (rows0-7,k0-7)(rows8-15,k0-7)(rows0-7,k8-15)(rows8-15,k8-15)
    int rowA   = (lane & 7) + 8 * ((lane >> 3) & 1);
    int kplusA = (lane >> 4) & 1;                    // +16B for k8-15 matrices
    // B (x2): matrices (n0-7,k0-7)(n0-7,k8-15); lanes>=16 unused (replicated)
    int rowB   = lane & 7;
    int kplusB = (lane >> 3) & 1;

    uint32_t aAh = smem_u32(Ah) + ((wm * 64 + rowA) * PADW + kplusA * 4) * 4;
    uint32_t aAl = aAh + TILE_W * 4;
    uint32_t aBh = smem_u32(Bh) + ((wn * 32 + rowB) * PADW + kplusB * 4) * 4;
    uint32_t aBl = aBh + TILE_W * 4;

    float acc[4][4][4];
#pragma unroll
    for (int a = 0; a < 4; ++a)
#pragma unroll
        for (int b = 0; b < 4; ++b)
#pragma unroll
            for (int c = 0; c < 4; ++c) acc[a][b][c] = 0.0f;

#pragma unroll
    for (int kt = 0; kt < 4; ++kt) {
        uint32_t ah[4][4], al[4][4];    // [mt][reg]
        uint32_t bh[4][2], bl[4][2];    // [nt][reg]
#pragma unroll
        for (int mt = 0; mt < 4; ++mt) {
            ldsm_x4(ah[mt], aAh + mt * A_MT_BYTES + kt * KT_BYTES);
            ldsm_x4(al[mt], aAl + mt * A_MT_BYTES + kt * KT_BYTES);
        }
#pragma unroll
        for (int nt = 0; nt < 4; ++nt) {
            ldsm_x2(bh[nt], aBh + nt * B_NT_BYTES + kt * KT_BYTES);
            ldsm_x2(bl[nt], aBl + nt * B_NT_BYTES + kt * KT_BYTES);
        }

        // pass-major issue: 16 independent MMAs per pass
#pragma unroll
        for (int mt = 0; mt < 4; ++mt)
#pragma unroll
            for (int nt = 0; nt < 4; ++nt)
                mma_bf16(acc[mt][nt], ah[mt], bh[nt]);   // hi*hi
#pragma unroll
        for (int mt = 0; mt < 4; ++mt)
#pragma unroll
            for (int nt = 0; nt < 4; ++nt)
                mma_bf16(acc[mt][nt], al[mt], bh[nt]);   // lo*hi
#pragma unroll
        for (int mt = 0; mt < 4; ++mt)
#pragma unroll
            for (int nt = 0; nt < 4; ++nt)
                mma_bf16(acc[mt][nt], ah[mt], bl[nt]);   // hi*lo
    }

    float bv = __ldg(bias);
    const size_t batch_stride = (size_t)S_DIM * N_DIM * N_DIM;

    // Epilogue: c0,c1 -> (row g, cols 2tg,2tg+1); c2,c3 -> row g+8
#pragma unroll
    for (int mt = 0; mt < 4; ++mt) {
#pragma unroll
        for (int h = 0; h < 2; ++h) {
            int i = i0 + wm * 64 + mt * 16 + g + 8 * h;
            size_t rowoff = ((size_t)s * N_DIM + i) * N_DIM;
#pragma unroll
            for (int nt = 0; nt < 4; ++nt) {
                int j = j0 + wn * 32 + nt * 8 + 2 * tg;
                float2 v;
                v.x = acc[mt][nt][2 * h + 0] + bv;
                v.y = acc[mt][nt][2 * h + 1] + bv;
                __stcs(reinterpret_cast<float2*>(&out[rowoff + j]), v);
                __stcs(reinterpret_cast<float2*>(&out[rowoff + j + batch_stride]), v);
            }
        }
    }
}

extern "C" void kernel_launch(void* const* d_in, const int* in_sizes, int n_in,
                              void* d_out, int out_size)
{
    const float* x0   = (const float*)d_in[0];  // tensor0 (S,N,D)
    const float* x1   = (const float*)d_in[1];  // tensor1 (S,N,D)
    const float* W    = (const float*)d_in[2];  // kernel  (D,D)
    const float* bias = (const float*)d_in[3];  // scalar
    float* out = (float*)d_out;                 // (2,S,N,N)

    cudaFuncSetAttribute(bilinear_mma_kernel,
                         cudaFuncAttributeMaxDynamicSharedMemorySize, SMEM_DYN);

    prep_kernel<<<256 + (S_DIM * N_DIM * D_DIM) / (256 * 4), 256>>>(x0, x1, W);

    dim3 grid(N_DIM / 128, N_DIM / 128, S_DIM);
    bilinear_mma_kernel<<<grid, 256, SMEM_DYN>>>(bias, out);
}